// round 17
// baseline (speedup 1.0000x reference)
#include <cuda_runtime.h>
#include <cuda_fp16.h>
#include <math.h>
#include <stdint.h>

#define BB 16
#define NN 2048
#define CC 128

// ---------------- device scratch ----------------
__device__ __half g_WsymH[CC * CC];            // 32 KB fp16 (pre-scaled by log2e)
__device__ __half g_Hh[BB * NN * CC];          // 8 MB fp16
__device__ __half g_biasH[(size_t)NN * NN];    // 8 MB fp16 (log2-domain)
__device__ __half g_scr[(size_t)BB * NN * NN]; // 134 MB unnormalized exp (fp16)

// ---------------- helpers ----------------
__device__ __forceinline__ uint32_t smem_u32(const void* p) {
    uint32_t a;
    asm("{ .reg .u64 t; cvta.to.shared.u64 t, %1; cvt.u32.u64 %0, t; }" : "=r"(a) : "l"(p));
    return a;
}
__device__ __forceinline__ void cpasync16(uint32_t s, const void* g) {
    asm volatile("cp.async.cg.shared.global [%0], [%1], 16;" :: "r"(s), "l"(g));
}
#define MBAR_INIT(a, c) \
    asm volatile("mbarrier.init.shared.b64 [%0], %1;" :: "r"(a), "r"(c) : "memory")
#define MBAR_ARRIVE(a) \
    asm volatile("mbarrier.arrive.shared.b64 _, [%0];" :: "r"(a) : "memory")
// .noinc: cp.async completion CONSUMES one preset arrival
#define CPASYNC_ARRIVE(a) \
    asm volatile("cp.async.mbarrier.arrive.noinc.shared.b64 [%0];" :: "r"(a) : "memory")
__device__ __forceinline__ void mbar_wait(uint32_t a, uint32_t parity) {
    asm volatile(
        "{\n\t.reg .pred P;\n\t"
        "WL_%=:\n\t"
        "mbarrier.try_wait.parity.shared.b64 P, [%0], %1;\n\t"
        "@P bra.uni WD_%=;\n\t"
        "bra.uni WL_%=;\n\t"
        "WD_%=:\n\t}"
        :: "r"(a), "r"(parity) : "memory");
}

__device__ __forceinline__ float ex2(float x) {
    float r;
    asm("ex2.approx.ftz.f32 %0, %1;" : "=f"(r) : "f"(x));
    return r;
}
__device__ __forceinline__ float2 h2_to_f2(uint32_t u) {
    __half2 h = *reinterpret_cast<__half2*>(&u);
    return __half22float2(h);
}

#define LDSM_X4(r0, r1, r2, r3, addr) \
    asm volatile("ldmatrix.sync.aligned.m8n8.x4.shared.b16 {%0,%1,%2,%3}, [%4];" \
        : "=r"(r0), "=r"(r1), "=r"(r2), "=r"(r3) : "r"(addr))

#define MMA16816(d, a, b0, b1) \
    asm volatile("mma.sync.aligned.m16n8k16.row.col.f32.f16.f16.f32 " \
        "{%0,%1,%2,%3}, {%4,%5,%6,%7}, {%8,%9}, {%0,%1,%2,%3};" \
        : "+f"((d)[0]), "+f"((d)[1]), "+f"((d)[2]), "+f"((d)[3]) \
        : "r"((a)[0]), "r"((a)[1]), "r"((a)[2]), "r"((a)[3]), "r"(b0), "r"(b1))

// smem layout
#define SM_S0     32768u
#define SM_S1     65536u
#define SM_ROWSUM 98304u
#define SM_INVS   100352u
#define SM_MBAR   100864u
#define SM_TOTAL  100928

// ---------------- W_sym (pre-scaled by log2e) ----------------
__global__ void k_wsym(const float* __restrict__ Wq, const float* __restrict__ Wk) {
    int k = blockIdx.x, c = threadIdx.x;
    float a1 = 0.f, a2 = 0.f;
    for (int e = 0; e < CC; e++) {
        a1 += Wq[e * CC + k] * Wk[e * CC + c];
        a2 += Wk[e * CC + k] * Wq[e * CC + c];
    }
    const float s = (0.5f / (sqrtf(128.0f) * 1.5f)) * 1.4426950408889634f;
    g_WsymH[k * CC + c] = __float2half(s * (a1 + a2));
}

// ---------------- H -> fp16 ----------------
__global__ void k_splitH(const float* __restrict__ H) {
    size_t i = ((size_t)blockIdx.x * blockDim.x + threadIdx.x) * 4;
    float4 v = *(const float4*)(H + i);
    __half2* dst = (__half2*)(g_Hh + i);
    dst[0] = __floats2half2_rn(v.x, v.y);
    dst[1] = __floats2half2_rn(v.z, v.w);
}

// ---------------- combined bias (fp16, log2 domain) ----------------
__global__ void k_bias(const float* __restrict__ Ast, const float* __restrict__ Mm) {
    size_t idx4 = (size_t)blockIdx.x * blockDim.x + threadIdx.x;
    int n = (int)(idx4 >> 9);
    int mb = (int)(idx4 & 511) * 4;
    float4 a = __ldcg((const float4*)Ast + idx4);
    float4 m = __ldcg((const float4*)Mm + idx4);
    const float L2E = 1.4426950408889634f;
    float ox = (m.x <= 0.f || mb + 0 == n) ? -60000.f : a.x * L2E;
    float oy = (m.y <= 0.f || mb + 1 == n) ? -60000.f : a.y * L2E;
    float oz = (m.z <= 0.f || mb + 2 == n) ? -60000.f : a.z * L2E;
    float ow = (m.w <= 0.f || mb + 3 == n) ? -60000.f : a.w * L2E;
    __half2 lo = __floats2half2_rn(ox, oy);
    __half2 hi = __floats2half2_rn(oz, ow);
    uint2 pack;
    pack.x = *reinterpret_cast<uint32_t*>(&lo);
    pack.y = *reinterpret_cast<uint32_t*>(&hi);
    __stcg((uint2*)(g_biasH + idx4 * 4), pack);
}

// ---------------- persistent main: designated-warp prefetch pipeline -----
// CTA = (rt, b). smem: bufA 32K | s0 32K | s1 32K | rowsum 2K | invs | mbars
// Per tile: ONE data-driven full-wait; free-wait + 32KB prefetch done by a
// single rotating warp, so the other 7 warps flow GEMM->epilogue->next wait.
__global__ void __launch_bounds__(256, 2) k_main(float* __restrict__ out) {
    extern __shared__ char smem[];
    uint32_t sm = smem_u32(smem);
    float* rowsum = (float*)(smem + SM_ROWSUM);   // [128][4]
    float* invs   = (float*)(smem + SM_INVS);
    uint32_t mb_fullA = sm + SM_MBAR;
    uint32_t mb_full0 = sm + SM_MBAR + 8;
    uint32_t mb_full1 = sm + SM_MBAR + 16;
    uint32_t mb_free0 = sm + SM_MBAR + 24;
    uint32_t mb_free1 = sm + SM_MBAR + 32;
    int tid = threadIdx.x, wid = tid >> 5, lane = tid & 31;
    int rt = blockIdx.x, b = blockIdx.y;

    if (tid == 0) {
        MBAR_INIT(mb_fullA, 256);   // armed by all 256 threads' cp.async
        MBAR_INIT(mb_full0, 32);    // armed by ONE warp's cp.async
        MBAR_INIT(mb_full1, 32);
        MBAR_INIT(mb_free0, 256);   // all threads arrive after reading
        MBAR_INIT(mb_free1, 256);
    }
    ((float2*)rowsum)[tid] = make_float2(0.f, 0.f);
    __syncthreads();   // mbarrier init visible

    const __half* Hrt = g_Hh + ((size_t)(b * NN + rt * 128)) * CC;

    // prologue: A -> bufA, Wsym -> s0 by ALL threads (fullA, count 256)
    #pragma unroll
    for (int it = 0; it < 8; it++) {
        int idx = it * 256 + tid;
        int m = idx >> 4, c = idx & 15;
        uint32_t dst = (uint32_t)(m * 256 + ((c ^ (m & 7)) << 4));
        cpasync16(sm + dst, Hrt + (size_t)idx * 8);
        cpasync16(sm + SM_S0 + dst, g_WsymH + idx * 8);
    }
    CPASYNC_ARRIVE(mb_fullA);
    // B(1) -> s1 by warp 1 only (full1, count 32)
    if (wid == 1) {
        const __half* Bp = g_Hh + ((size_t)(b * NN + 128)) * CC;
        #pragma unroll
        for (int it = 0; it < 64; it++) {
            int idx = it * 32 + lane;
            int m = idx >> 4, c = idx & 15;
            uint32_t dst = (uint32_t)(m * 256 + ((c ^ (m & 7)) << 4));
            cpasync16(sm + SM_S1 + dst, Bp + (size_t)idx * 8);
        }
        CPASYNC_ARRIVE(mb_full1);
    }

    int wm = wid >> 2, wn = wid & 3;          // warp tile 64(m) x 32(n)
    int mo = wm * 64, no = wn * 32;
    int lr = lane & 15, cb = lane >> 4, l7 = lane & 7;
    int q = lane >> 2, qq = (lane & 3) * 2;

    uint32_t rowAoff[4], rowBoff[2];
    #pragma unroll
    for (int i = 0; i < 4; i++) rowAoff[i] = (uint32_t)(mo + i * 16 + lr) * 256u;
    #pragma unroll
    for (int j = 0; j < 2; j++) rowBoff[j] = (uint32_t)(no + j * 16 + lr) * 256u;

    float acc[4][4][4];

    // ---- Phase 1: G = H_rt @ Wsym (A in bufA, Wsym in s0) ----
    mbar_wait(mb_fullA, 0);
    __syncthreads();
    #pragma unroll
    for (int i = 0; i < 4; i++)
        #pragma unroll
        for (int j = 0; j < 4; j++)
            #pragma unroll
            for (int p = 0; p < 4; p++) acc[i][j][p] = 0.f;
    #pragma unroll
    for (int ks = 0; ks < 8; ks++) {
        uint32_t sw = (uint32_t)(((2 * ks + cb) ^ l7) << 4);
        uint32_t a[4][4], bf[2][4];
        #pragma unroll
        for (int i = 0; i < 4; i++)
            LDSM_X4(a[i][0], a[i][1], a[i][2], a[i][3], sm + rowAoff[i] + sw);
        #pragma unroll
        for (int j = 0; j < 2; j++)
            LDSM_X4(bf[j][0], bf[j][1], bf[j][2], bf[j][3], sm + SM_S0 + rowBoff[j] + sw);
        #pragma unroll
        for (int i = 0; i < 4; i++)
            #pragma unroll
            for (int j = 0; j < 4; j++)
                MMA16816(acc[i][j], a[i], bf[j >> 1][j & 1], bf[j >> 1][2 + (j & 1)]);
    }
    __syncthreads();   // all reads of bufA/s0 done

    // store G fragments into bufA (fp16, swizzled A layout)
    #pragma unroll
    for (int i = 0; i < 4; i++) {
        int r1 = mo + i * 16 + q;
        #pragma unroll
        for (int j = 0; j < 4; j++) {
            int c = no + j * 8 + qq;
            uint32_t ch = (uint32_t)(c >> 3);
            uint32_t off1 = (uint32_t)r1 * 256u + ((ch ^ ((uint32_t)r1 & 7)) << 4) + (uint32_t)(c & 7) * 2u;
            int r2 = r1 + 8;
            uint32_t off2 = (uint32_t)r2 * 256u + ((ch ^ ((uint32_t)r2 & 7)) << 4) + (uint32_t)(c & 7) * 2u;
            *(__half2*)(smem + off1) = __floats2half2_rn(acc[i][j][0], acc[i][j][1]);
            *(__half2*)(smem + off2) = __floats2half2_rn(acc[i][j][2], acc[i][j][3]);
        }
    }
    // B(0) -> s0 by warp 0 only (Wsym dead after the sync above)
    if (wid == 0) {
        const __half* Bp = g_Hh + (size_t)(b * NN) * CC;
        #pragma unroll
        for (int it = 0; it < 64; it++) {
            int idx = it * 32 + lane;
            int m = idx >> 4, c = idx & 15;
            uint32_t dst = (uint32_t)(m * 256 + ((c ^ (m & 7)) << 4));
            cpasync16(sm + SM_S0 + dst, Bp + (size_t)idx * 8);
        }
        CPASYNC_ARRIVE(mb_full0);
    }
    __syncthreads();   // G stores visible to all warps

    // ---- pipelined GEMM pass: t = 0..15 ----
    size_t obase = (size_t)b * NN * NN;

    #pragma unroll 1
    for (int t = 0; t < 16; t++) {
        uint32_t slot = sm + SM_S0 + (uint32_t)((t & 1) << 15);
        uint32_t mb_full = (t & 1) ? mb_full1 : mb_full0;
        uint32_t mb_free = (t & 1) ? mb_free1 : mb_free0;
        uint32_t parity = (uint32_t)((t >> 1) & 1);

        mbar_wait(mb_full, parity);   // B(t) resident (single data-driven wait)

        #pragma unroll
        for (int i = 0; i < 4; i++)
            #pragma unroll
            for (int j = 0; j < 4; j++)
                #pragma unroll
                for (int p = 0; p < 4; p++) acc[i][j][p] = 0.f;
        #pragma unroll
        for (int ks = 0; ks < 8; ks++) {
            uint32_t sw = (uint32_t)(((2 * ks + cb) ^ l7) << 4);
            uint32_t a[4][4], bf[2][4];
            #pragma unroll
            for (int i = 0; i < 4; i++)
                LDSM_X4(a[i][0], a[i][1], a[i][2], a[i][3], sm + rowAoff[i] + sw);
            #pragma unroll
            for (int j = 0; j < 2; j++)
                LDSM_X4(bf[j][0], bf[j][1], bf[j][2], bf[j][3], slot + rowBoff[j] + sw);
            #pragma unroll
            for (int i = 0; i < 4; i++)
                #pragma unroll
                for (int j = 0; j < 4; j++)
                    MMA16816(acc[i][j], a[i], bf[j >> 1][j & 1], bf[j >> 1][2 + (j & 1)]);
        }
        MBAR_ARRIVE(mb_free);   // non-blocking: this thread done reading slot

        // ONLY the rotating designated warp waits for the slot to drain and
        // prefetches B(t+2); all other warps go straight to the epilogue.
        if (t < 14 && wid == (t & 7)) {
            mbar_wait(mb_free, parity);
            const __half* Bp = g_Hh + ((size_t)(b * NN + (t + 2) * 128)) * CC;
            #pragma unroll
            for (int it = 0; it < 64; it++) {
                int idx = it * 32 + lane;
                int m = idx >> 4, c = idx & 15;
                uint32_t dst = (uint32_t)(m * 256 + ((c ^ (m & 7)) << 4));
                cpasync16(slot + dst, Bp + (size_t)idx * 8);
            }
            CPASYNC_ARRIVE(mb_full);
        }

        // epilogue: exp2(acc + bias) -> fp16 scratch + rowsum
        int gc0 = t * 128 + no;
        #pragma unroll
        for (int i = 0; i < 4; i++) {
            int lrow = mo + i * 16 + q;
            int r1 = rt * 128 + lrow, r2 = r1 + 8;
            const __half* b1p = g_biasH + (size_t)r1 * NN;
            const __half* b2p = g_biasH + (size_t)r2 * NN;
            __half* s1p = g_scr + obase + (size_t)r1 * NN;
            __half* s2p = g_scr + obase + (size_t)r2 * NN;
            float s1 = 0.f, s2 = 0.f;
            #pragma unroll
            for (int j = 0; j < 4; j++) {
                int c = gc0 + j * 8 + qq;
                float2 bb1 = __half22float2(*(const __half2*)(b1p + c));
                float2 bb2 = __half22float2(*(const __half2*)(b2p + c));
                float e0 = ex2(acc[i][j][0] + bb1.x);
                float e1 = ex2(acc[i][j][1] + bb1.y);
                float e2 = ex2(acc[i][j][2] + bb2.x);
                float e3 = ex2(acc[i][j][3] + bb2.y);
                *(__half2*)(s1p + c) = __floats2half2_rn(e0, e1);
                *(__half2*)(s2p + c) = __floats2half2_rn(e2, e3);
                s1 += e0 + e1;
                s2 += e2 + e3;
            }
            #pragma unroll
            for (int o = 1; o < 4; o <<= 1) {
                s1 += __shfl_xor_sync(0xffffffffu, s1, o);
                s2 += __shfl_xor_sync(0xffffffffu, s2, o);
            }
            if ((lane & 3) == 0) {
                rowsum[lrow * 4 + wn] += s1;
                rowsum[(lrow + 8) * 4 + wn] += s2;
            }
        }
    }
    __syncthreads();

    // ---- 1/rowsum ----
    if (tid < 128) {
        float s = rowsum[tid * 4] + rowsum[tid * 4 + 1]
                + rowsum[tid * 4 + 2] + rowsum[tid * 4 + 3];
        invs[tid] = 1.0f / s;
    }
    __syncthreads();

    // ---- streaming renorm: out = inv[row] * scr (fp16 -> fp32) ----
    const uint4* sp4 = (const uint4*)(g_scr + obase + (size_t)(rt * 128) * NN);
    float4* op4 = (float4*)(out + obase + (size_t)(rt * 128) * NN);
    #pragma unroll 4
    for (int idx = tid; idx < 128 * 256; idx += 256) {
        int row = idx >> 8;
        float inv = invs[row];
        uint4 v = sp4[idx];
        float2 f0 = h2_to_f2(v.x), f1 = h2_to_f2(v.y);
        float2 f2 = h2_to_f2(v.z), f3 = h2_to_f2(v.w);
        __stcg(op4 + idx * 2 + 0, make_float4(f0.x * inv, f0.y * inv, f1.x * inv, f1.y * inv));
        __stcg(op4 + idx * 2 + 1, make_float4(f2.x * inv, f2.y * inv, f3.x * inv, f3.y * inv));
    }
}

// ---------------- launch ----------------
extern "C" void kernel_launch(void* const* d_in, const int* in_sizes, int n_in,
                              void* d_out, int out_size) {
    const float* H   = (const float*)d_in[0];
    const float* Ast = (const float*)d_in[1];
    const float* Mm  = (const float*)d_in[2];
    const float* Wq  = (const float*)d_in[3];
    const float* Wk  = (const float*)d_in[4];
    float* out = (float*)d_out;

    static bool attr_done = false;
    if (!attr_done) {
        cudaFuncSetAttribute(k_main, cudaFuncAttributeMaxDynamicSharedMemorySize, SM_TOTAL);
        attr_done = true;
    }

    k_wsym<<<CC, CC>>>(Wq, Wk);
    k_splitH<<<(BB * NN * CC / 4) / 256, 256>>>(H);
    k_bias<<<((size_t)NN * NN / 4) / 256, 256>>>(Ast, Mm);
    {
        dim3 grid(NN / 128, BB);   // (rt, b)
        k_main<<<grid, 256, SM_TOTAL>>>(out);
    }
}